// round 9
// baseline (speedup 1.0000x reference)
#include <cuda_runtime.h>
#include <cuda_bf16.h>
#include <math.h>
#include <cstdint>

#define NQ 8
#define DIM 256
#define NL 6
#define MAXB 8192

typedef unsigned long long u64;

// ---------------- scratch ----------------
__device__ float  g_nrm2[MAXB];
__device__ __nv_bfloat16 g_xhi[MAXB * 256];
__device__ __nv_bfloat16 g_xlo[MAXB * 256];
__device__ __nv_bfloat16 g_Whi[512 * 256];   // row n=2j -> Re U[j,:], n=2j+1 -> Im U[j,:]
__device__ __nv_bfloat16 g_Wlo[512 * 256];
__device__ float4 g_eqp4[4 * MAXB];          // e partials per N-quarter (nb)
__device__ float  g_y1[MAXB * 32];
__device__ float  g_part1[(MAXB / 64) * 64];
__device__ float  g_part2[(MAXB / 256) * 32];
__device__ unsigned g_arrive;
__device__ unsigned g_depart;

// ---------------- helpers ----------------
__device__ __forceinline__ uint32_t smem_to_u32(const void* p) {
    uint32_t a;
    asm("{ .reg .u64 t; cvta.to.shared.u64 t, %1; cvt.u32.u64 %0, t; }" : "=r"(a) : "l"(p));
    return a;
}
#define SWZ(bo) ((bo) ^ (((bo) >> 3) & 0x70))

#define LDMX4(r, a) \
    asm volatile("ldmatrix.sync.aligned.m8n8.x4.shared.b16 {%0,%1,%2,%3}, [%4];" \
        : "=r"((r)[0]), "=r"((r)[1]), "=r"((r)[2]), "=r"((r)[3]) : "r"(a))
#define LDMX2(r, a) \
    asm volatile("ldmatrix.sync.aligned.m8n8.x2.shared.b16 {%0,%1}, [%2];" \
        : "=r"((r)[0]), "=r"((r)[1]) : "r"(a))
#define MMA_BF16(d, a, b) \
    asm volatile("mma.sync.aligned.m16n8k16.row.col.f32.bf16.bf16.f32 " \
        "{%0,%1,%2,%3},{%4,%5,%6,%7},{%8,%9},{%0,%1,%2,%3};" \
        : "+f"((d)[0]), "+f"((d)[1]), "+f"((d)[2]), "+f"((d)[3]) \
        : "r"((a)[0]), "r"((a)[1]), "r"((a)[2]), "r"((a)[3]), "r"((b)[0]), "r"((b)[1]))

__device__ __forceinline__ float2 cmul(float2 a, float2 b) {
    return make_float2(a.x * b.x - a.y * b.y, a.x * b.y + a.y * b.x);
}
__device__ __forceinline__ float2 cadd(float2 a, float2 b) {
    return make_float2(a.x + b.x, a.y + b.y);
}
__device__ __forceinline__ u64 fma2(u64 a, u64 b, u64 c) {
    u64 d; asm("fma.rn.f32x2 %0,%1,%2,%3;" : "=l"(d) : "l"(a), "l"(b), "l"(c)); return d;
}
__device__ __forceinline__ u64 mul2(u64 a, u64 b) {
    u64 d; asm("mul.rn.f32x2 %0,%1,%2;" : "=l"(d) : "l"(a), "l"(b)); return d;
}
__device__ __forceinline__ u64 pack2(float lo, float hi) {
    u64 d; asm("mov.b64 %0,{%1,%2};" : "=l"(d) : "f"(lo), "f"(hi)); return d;
}
__device__ __forceinline__ float2 unpack2(u64 v) {
    float2 r; asm("mov.b64 {%0,%1},%2;" : "=f"(r.x), "=f"(r.y) : "l"(v)); return r;
}
__device__ __forceinline__ u64 splat2(float v) { return pack2(v, v); }
__device__ __forceinline__ u64 swap2(u64 v) { float2 r = unpack2(v); return pack2(r.y, r.x); }
__device__ __forceinline__ u64 shflxor2(u64 v, int m) { return __shfl_xor_sync(0xffffffffu, v, m); }
__device__ __forceinline__ void bf16_split(float v, __nv_bfloat16& hi, __nv_bfloat16& lo) {
    hi = __float2bfloat16_rn(v);
    lo = __float2bfloat16_rn(v - __bfloat162float(hi));
}

// ---------------- K1: prep — x split (blocks < convB) + basis sim (rest) -----
__global__ __launch_bounds__(256) void k_prep(const float* __restrict__ x,
                                              const float* __restrict__ qw, int convB) {
    __shared__ float2 gsh[NL * NQ * 4];
    __shared__ float  sre[8][256];
    __shared__ float  sim_[8][256];

    int t = threadIdx.x, w = t >> 5, l = t & 31;

    if ((int)blockIdx.x < convB) {
        int b = blockIdx.x * 8 + w;
        const float4* xp = (const float4*)(x + (size_t)b * 256 + l * 8);
        float4 v0 = xp[0], v1 = xp[1];
        float nr = v0.x*v0.x + v0.y*v0.y + v0.z*v0.z + v0.w*v0.w
                 + v1.x*v1.x + v1.y*v1.y + v1.z*v1.z + v1.w*v1.w;
        #pragma unroll
        for (int o = 16; o; o >>= 1) nr += __shfl_xor_sync(0xffffffffu, nr, o);
        if (l == 0) g_nrm2[b] = nr;
        float vv[8] = {v0.x, v0.y, v0.z, v0.w, v1.x, v1.y, v1.z, v1.w};
        unsigned hw[4], lw[4];
        #pragma unroll
        for (int i = 0; i < 4; i++) {
            __nv_bfloat16 h0, l0, h1, l1;
            bf16_split(vv[2*i], h0, l0);
            bf16_split(vv[2*i+1], h1, l1);
            hw[i] = (unsigned)__bfloat16_as_ushort(h0) | ((unsigned)__bfloat16_as_ushort(h1) << 16);
            lw[i] = (unsigned)__bfloat16_as_ushort(l0) | ((unsigned)__bfloat16_as_ushort(l1) << 16);
        }
        size_t off = (size_t)b * 256 + l * 8;
        *((uint4*)(g_xhi + off)) = make_uint4(hw[0], hw[1], hw[2], hw[3]);
        *((uint4*)(g_xlo + off)) = make_uint4(lw[0], lw[1], lw[2], lw[3]);
        return;
    }

    // basis sim: warp simulates basis state k -> column k of U (verified core)
    if (t < NL * NQ) {
        int lay = t >> 3, q = t & 7;
        float tx = 0.5f * qw[lay * 24 + q * 3 + 0];
        float ty = 0.5f * qw[lay * 24 + q * 3 + 1];
        float tz = 0.5f * qw[lay * 24 + q * 3 + 2];
        float cx = cosf(tx), sx = sinf(tx);
        float cy = cosf(ty), sy = sinf(ty);
        float cz = cosf(tz), sz = sinf(tz);
        float2 RX0 = make_float2(cx, 0.f), RX1 = make_float2(0.f, -sx);
        float2 RX2 = make_float2(0.f, -sx), RX3 = make_float2(cx, 0.f);
        float2 RY0 = make_float2(cy, 0.f), RY1 = make_float2(-sy, 0.f);
        float2 RY2 = make_float2(sy, 0.f), RY3 = make_float2(cy, 0.f);
        float2 RZ0 = make_float2(cz, -sz), RZ3 = make_float2(cz, sz);
        float2 M0 = cadd(cmul(RY0, RX0), cmul(RY1, RX2));
        float2 M1 = cadd(cmul(RY0, RX1), cmul(RY1, RX3));
        float2 M2 = cadd(cmul(RY2, RX0), cmul(RY3, RX2));
        float2 M3 = cadd(cmul(RY2, RX1), cmul(RY3, RX3));
        gsh[t * 4 + 0] = cmul(RZ0, M0);
        gsh[t * 4 + 1] = cmul(RZ0, M1);
        gsh[t * 4 + 2] = cmul(RZ3, M2);
        gsh[t * 4 + 3] = cmul(RZ3, M3);
    }

    int k = (blockIdx.x - convB) * 8 + w;

    u64 xv[4], yv[4];
    #pragma unroll
    for (int v = 0; v < 4; v++) {
        float a0 = (l == (k >> 3) && (k & 7) == 2 * v)     ? 1.f : 0.f;
        float a1 = (l == (k >> 3) && (k & 7) == 2 * v + 1) ? 1.f : 0.f;
        xv[v] = pack2(a0, a1);
        yv[v] = 0ull;
    }

    const int cbs[11] = {3, 5, 7, 0, 1, 2, 3, 4, 5, 6, 7};
    const int tbs[11] = {1, 3, 5, 7, 0, 1, 2, 3, 4, 5, 6};
    int rslot[8];
    #pragma unroll
    for (int jj = 0; jj < 8; jj++) {
        int p = l * 8 + jj;
        #pragma unroll
        for (int gi = 0; gi < 11; gi++)
            p ^= ((p >> cbs[gi]) & 1) << tbs[gi];
        rslot[jj] = ((p & 7) << 5) | (p >> 3);
    }

    __syncthreads();

    for (int lay = 0; lay < NL; lay++) {
        #pragma unroll
        for (int q = 0; q < NQ; q++) {
            const int bp = 7 - q;
            const float2* U = &gsh[(lay * 8 + q) * 4];
            float2 u0 = U[0], u1 = U[1], u2 = U[2], u3 = U[3];
            if (bp >= 3) {
                int msk = 1 << (bp - 3);
                int myb = (l >> (bp - 3)) & 1;
                float2 uA = myb ? u3 : u0;
                float2 uB = myb ? u2 : u1;
                u64 uAx = splat2(uA.x), uAy = splat2(uA.y), nuAy = splat2(-uA.y);
                u64 uBx = splat2(uB.x), uBy = splat2(uB.y), nuBy = splat2(-uB.y);
                #pragma unroll
                for (int v = 0; v < 4; v++) {
                    u64 px = shflxor2(xv[v], msk);
                    u64 py = shflxor2(yv[v], msk);
                    u64 nx = fma2(uAx, xv[v], fma2(nuAy, yv[v], fma2(uBx, px, mul2(nuBy, py))));
                    u64 ny = fma2(uAx, yv[v], fma2(uAy, xv[v], fma2(uBx, py, mul2(uBy, px))));
                    xv[v] = nx; yv[v] = ny;
                }
            } else if (bp >= 1) {
                u64 u0x = splat2(u0.x), u0y = splat2(u0.y), nu0y = splat2(-u0.y);
                u64 u1x = splat2(u1.x), u1y = splat2(u1.y), nu1y = splat2(-u1.y);
                u64 u2x = splat2(u2.x), u2y = splat2(u2.y), nu2y = splat2(-u2.y);
                u64 u3x = splat2(u3.x), u3y = splat2(u3.y), nu3y = splat2(-u3.y);
                #pragma unroll
                for (int pr = 0; pr < 2; pr++) {
                    int a = (bp == 1) ? (pr * 2) : pr;
                    int c = (bp == 1) ? (pr * 2 + 1) : (pr + 2);
                    u64 ax = xv[a], ay = yv[a], bx = xv[c], by = yv[c];
                    xv[a] = fma2(u0x, ax, fma2(nu0y, ay, fma2(u1x, bx, mul2(nu1y, by))));
                    yv[a] = fma2(u0x, ay, fma2(u0y, ax, fma2(u1x, by, mul2(u1y, bx))));
                    xv[c] = fma2(u2x, ax, fma2(nu2y, ay, fma2(u3x, bx, mul2(nu3y, by))));
                    yv[c] = fma2(u2x, ay, fma2(u2y, ax, fma2(u3x, by, mul2(u3y, bx))));
                }
            } else {
                u64 Ax = pack2(u0.x, u3.x), Ay = pack2(u0.y, u3.y), nAy = pack2(-u0.y, -u3.y);
                u64 Bx = pack2(u1.x, u2.x), By = pack2(u1.y, u2.y), nBy = pack2(-u1.y, -u2.y);
                #pragma unroll
                for (int v = 0; v < 4; v++) {
                    u64 xs_ = swap2(xv[v]);
                    u64 ys_ = swap2(yv[v]);
                    u64 nx = fma2(Ax, xv[v], fma2(nAy, yv[v], fma2(Bx, xs_, mul2(nBy, ys_))));
                    u64 ny = fma2(Ax, yv[v], fma2(Ay, xv[v], fma2(Bx, ys_, mul2(By, xs_))));
                    xv[v] = nx; yv[v] = ny;
                }
            }
        }
        __syncwarp();
        #pragma unroll
        for (int v = 0; v < 4; v++) {
            float2 rx = unpack2(xv[v]), ry = unpack2(yv[v]);
            sre[w][(2 * v) * 32 + l]      = rx.x;
            sre[w][(2 * v + 1) * 32 + l]  = rx.y;
            sim_[w][(2 * v) * 32 + l]     = ry.x;
            sim_[w][(2 * v + 1) * 32 + l] = ry.y;
        }
        __syncwarp();
        #pragma unroll
        for (int v = 0; v < 4; v++) {
            xv[v] = pack2(sre[w][rslot[2 * v]], sre[w][rslot[2 * v + 1]]);
            yv[v] = pack2(sim_[w][rslot[2 * v]], sim_[w][rslot[2 * v + 1]]);
        }
    }

    #pragma unroll
    for (int v = 0; v < 4; v++) {
        float2 rx = unpack2(xv[v]), ry = unpack2(yv[v]);
        int j0 = 8 * l + 2 * v;
        float vals[4] = {rx.x, ry.x, rx.y, ry.y};
        #pragma unroll
        for (int r = 0; r < 4; r++) {
            __nv_bfloat16 hi, lo;
            bf16_split(vals[r], hi, lo);
            size_t row = (size_t)(2 * j0 + r);
            g_Whi[row * 256 + k] = hi;
            g_Wlo[row * 256 + k] = lo;
        }
    }
}

// ---------------- K2: mma.sync GEMM (W x) + expectation epilogue -------------
// CTA: 128 samples x 128 W-rows (nb = N-quarter), K=256 in 4 staged chunks.
#define GS_A0 0
#define GS_A1 16384
#define GS_B0 32768
#define GS_B1 49152
#define GEMM_SMEM 65536

__global__ __launch_bounds__(256) void k_gemm(int B) {
    extern __shared__ __align__(16) char smg[];
    uint32_t sb = smem_to_u32(smg);
    int tid = threadIdx.x;
    int w = tid >> 5, l = tid & 31;
    int tile = blockIdx.x >> 2, nb = blockIdx.x & 3;
    int S0 = tile * 128;

    // per-lane ldmatrix address components
    int r8  = l & 7, grp = l >> 3;
    int rowA = r8 + ((grp & 1) << 3);   // row within 16-row m-tile
    int colA = (grp & 2) << 3;          // 0 or 16 bytes (k+8)
    int rowB = l & 7;
    int colB = ((l >> 3) & 1) << 4;

    float acc[8][2][4];
    #pragma unroll
    for (int mt = 0; mt < 8; mt++)
        #pragma unroll
        for (int nt = 0; nt < 2; nt++)
            #pragma unroll
            for (int c = 0; c < 4; c++) acc[mt][nt][c] = 0.f;

    for (int kc = 0; kc < 4; kc++) {
        for (int i = tid; i < 1024; i += 256) {
            int row = i >> 3, seg = i & 7;
            size_t srcA = (size_t)(S0 + row) * 256 + kc * 64 + seg * 8;
            size_t srcB = (size_t)(nb * 128 + row) * 256 + kc * 64 + seg * 8;
            uint32_t dst = SWZ((uint32_t)(row * 128 + seg * 16));
            *(uint4*)(smg + GS_A0 + dst) = *(const uint4*)(g_xhi + srcA);
            *(uint4*)(smg + GS_A1 + dst) = *(const uint4*)(g_xlo + srcA);
            *(uint4*)(smg + GS_B0 + dst) = *(const uint4*)(g_Whi + srcB);
            *(uint4*)(smg + GS_B1 + dst) = *(const uint4*)(g_Wlo + srcB);
        }
        __syncthreads();
        #pragma unroll
        for (int ks = 0; ks < 4; ks++) {
            uint32_t bh[2][2], bl[2][2];
            #pragma unroll
            for (int nt = 0; nt < 2; nt++) {
                uint32_t boff = SWZ((uint32_t)((w * 16 + nt * 8 + rowB) * 128 + ks * 32 + colB));
                LDMX2(bh[nt], sb + GS_B0 + boff);
                LDMX2(bl[nt], sb + GS_B1 + boff);
            }
            #pragma unroll
            for (int mt = 0; mt < 8; mt++) {
                uint32_t aoff = SWZ((uint32_t)((mt * 16 + rowA) * 128 + ks * 32 + colA));
                uint32_t ah[4], al[4];
                LDMX4(ah, sb + GS_A0 + aoff);
                LDMX4(al, sb + GS_A1 + aoff);
                #pragma unroll
                for (int nt = 0; nt < 2; nt++) {
                    MMA_BF16(acc[mt][nt], ah, bh[nt]);
                    MMA_BF16(acc[mt][nt], ah, bl[nt]);
                    MMA_BF16(acc[mt][nt], al, bh[nt]);
                }
            }
        }
        __syncthreads();
    }

    // epilogue: P = re^2 + im^2 per lane (adjacent cols), signed reductions
    float* e_s = (float*)smg;   // [8 warps][128 m][4] — aliases A0 (16KB)
    #pragma unroll
    for (int mt = 0; mt < 8; mt++) {
        float sa0 = 0.f, sa1 = 0.f, sa2 = 0.f, sa3 = 0.f;
        float sb0 = 0.f, sb1 = 0.f, sb2 = 0.f, sb3 = 0.f;
        #pragma unroll
        for (int nt = 0; nt < 2; nt++) {
            float c0 = acc[mt][nt][0], c1 = acc[mt][nt][1];
            float c2 = acc[mt][nt][2], c3 = acc[mt][nt][3];
            float Pa = c0 * c0 + c1 * c1;
            float Pb = c2 * c2 + c3 * c3;
            int j = nb * 64 + w * 8 + nt * 4 + (l & 3);
            float f0 = (j & 128) ? -1.f : 1.f;
            float f1 = (j & 64)  ? -1.f : 1.f;
            float f2 = (j & 32)  ? -1.f : 1.f;
            float f3 = (j & 16)  ? -1.f : 1.f;
            sa0 += f0 * Pa; sa1 += f1 * Pa; sa2 += f2 * Pa; sa3 += f3 * Pa;
            sb0 += f0 * Pb; sb1 += f1 * Pb; sb2 += f2 * Pb; sb3 += f3 * Pb;
        }
        #define REDL(v) { v += __shfl_xor_sync(0xffffffffu, v, 1); v += __shfl_xor_sync(0xffffffffu, v, 2); }
        REDL(sa0) REDL(sa1) REDL(sa2) REDL(sa3)
        REDL(sb0) REDL(sb1) REDL(sb2) REDL(sb3)
        if ((l & 3) == 0) {
            int m1 = mt * 16 + (l >> 2);
            float* p1 = e_s + (w * 128 + m1) * 4;
            p1[0] = sa0; p1[1] = sa1; p1[2] = sa2; p1[3] = sa3;
            float* p2 = e_s + (w * 128 + m1 + 8) * 4;
            p2[0] = sb0; p2[1] = sb1; p2[2] = sb2; p2[3] = sb3;
        }
    }
    __syncthreads();
    if (tid < 128) {
        float4 r = make_float4(0.f, 0.f, 0.f, 0.f);
        #pragma unroll
        for (int w8 = 0; w8 < 8; w8++) {
            const float* p = e_s + (w8 * 128 + tid) * 4;
            r.x += p[0]; r.y += p[1]; r.z += p[2]; r.w += p[3];
        }
        g_eqp4[nb * MAXB + S0 + tid] = r;
    }
}

// ---------------- K3: feature processor + adapter + fc1 + BN1 partials -------
#define FEAT_SMEM (64*260*4 + 64*68*4 + 2048)

__global__ __launch_bounds__(256, 2) void k_feat(
    const float* __restrict__ x,
    const float* __restrict__ aW, const float* __restrict__ ab,
    const float* __restrict__ fW1, const float* __restrict__ fb1,
    const float* __restrict__ fW2, const float* __restrict__ fb2,
    const float* __restrict__ cW1, const float* __restrict__ cb1, int B)
{
    extern __shared__ __align__(16) char sm[];
    float (*xs)[260] = (float(*)[260])sm;
    float (*ws)[68]  = (float(*)[68])(sm + 66560);
    float *cst       = (float*)(sm + 83968);
    float *fw2s = cst;
    float *cw1s = cst + 256;
    float *fb1s = cst + 384;
    float *cb1s = cst + 448;
    float *fb2s = cst + 480;
    float *abs_ = cst + 484;
    float *aWs  = cst + 488;
    float (*h1s)[68] = (float(*)[68])sm;
    float (*hs)[8]   = (float(*)[8])(sm + 20480);
    float (*ys)[33]  = (float(*)[33])(sm + 24576);

    int tid = threadIdx.x;
    int S0 = blockIdx.x * 64;
    int w = tid >> 5, l = tid & 31;

    fw2s[tid] = fW2[tid];
    if (tid < 128) cw1s[tid] = cW1[tid];
    if (tid < 64)  fb1s[tid] = fb1[tid];
    if (tid < 32)  cb1s[tid] = cb1[tid];
    if (tid < 16)  aWs[tid]  = aW[tid];
    if (tid < 4) { fb2s[tid] = fb2[tid]; abs_[tid] = ab[tid]; }

    for (int i = tid; i < 64 * 64; i += 256) {
        int s = i >> 6, q = i & 63;
        ((float4*)&xs[s][0])[q] = ((const float4*)(x + (size_t)(S0 + s) * 256))[q];
    }

    u64 acc[2][8];
    #pragma unroll
    for (int sg = 0; sg < 2; sg++)
        #pragma unroll
        for (int j = 0; j < 8; j++) acc[sg][j] = 0ull;

    for (int kc = 0; kc < 4; kc++) {
        __syncthreads();
        for (int i = tid; i < 64 * 16; i += 256) {
            int o = i >> 4, q = i & 15;
            ((float4*)&ws[o][0])[q] = ((const float4*)(fW1 + o * 256 + kc * 64))[q];
        }
        __syncthreads();
        const float4* xr0 = (const float4*)&xs[l][kc * 64];
        const float4* xr1 = (const float4*)&xs[l + 32][kc * 64];
        #pragma unroll
        for (int q = 0; q < 16; q++) {
            float4 a4 = xr0[q], b4 = xr1[q];
            u64 x0lo = pack2(a4.x, a4.y), x0hi = pack2(a4.z, a4.w);
            u64 x1lo = pack2(b4.x, b4.y), x1hi = pack2(b4.z, b4.w);
            #pragma unroll
            for (int j = 0; j < 8; j++) {
                float4 w4 = ((const float4*)&ws[w * 8 + j][0])[q];
                u64 wlo = pack2(w4.x, w4.y), whi = pack2(w4.z, w4.w);
                acc[0][j] = fma2(wlo, x0lo, acc[0][j]);
                acc[0][j] = fma2(whi, x0hi, acc[0][j]);
                acc[1][j] = fma2(wlo, x1lo, acc[1][j]);
                acc[1][j] = fma2(whi, x1hi, acc[1][j]);
            }
        }
    }
    __syncthreads();

    #pragma unroll
    for (int sg = 0; sg < 2; sg++) {
        int s = l + 32 * sg;
        #pragma unroll
        for (int j = 0; j < 8; j++) {
            float2 r = unpack2(acc[sg][j]);
            h1s[s][w * 8 + j] = fmaxf(r.x + r.y + fb1s[w * 8 + j], 0.f);
        }
    }
    __syncthreads();

    {
        int s = tid & 63, j = tid >> 6;
        float a = fb2s[j];
        const float4* hp = (const float4*)&h1s[s][0];
        const float4* wp = (const float4*)&fw2s[j * 64];
        #pragma unroll
        for (int q = 0; q < 16; q++) {
            float4 h = hp[q], wv = wp[q];
            a += h.x * wv.x + h.y * wv.y + h.z * wv.z + h.w * wv.w;
        }
        float cf = tanhf(a);
        float4 q0 = g_eqp4[0 * MAXB + S0 + s];
        float4 q1 = g_eqp4[1 * MAXB + S0 + s];
        float4 q2 = g_eqp4[2 * MAXB + S0 + s];
        float4 q3 = g_eqp4[3 * MAXB + S0 + s];
        float inv = 1.f / g_nrm2[S0 + s];
        float qx = (q0.x + q1.x + q2.x + q3.x) * inv;
        float qy = (q0.y + q1.y + q2.y + q3.y) * inv;
        float qz = (q0.z + q1.z + q2.z + q3.z) * inv;
        float qw = (q0.w + q1.w + q2.w + q3.w) * inv;
        float qf = abs_[j] + aWs[j * 4 + 0] * qx + aWs[j * 4 + 1] * qy
                           + aWs[j * 4 + 2] * qz + aWs[j * 4 + 3] * qw;
        hs[s][j] = cf + qf;
    }
    __syncthreads();

    for (int i = tid; i < 64 * 32; i += 256) {
        int s = i >> 5, o = i & 31;
        float vv = cb1s[o];
        #pragma unroll
        for (int k = 0; k < 4; k++) vv += hs[s][k] * cw1s[o * 4 + k];
        g_y1[(size_t)(S0 + s) * 32 + o] = vv;
        ys[s][o] = vv;
    }
    __syncthreads();

    if (tid < 32) {
        float su = 0.f, sq = 0.f;
        #pragma unroll
        for (int s = 0; s < 64; s++) {
            float vv = ys[s][tid];
            su += vv; sq += vv * vv;
        }
        g_part1[blockIdx.x * 64 + tid]      = su;
        g_part1[blockIdx.x * 64 + 32 + tid] = sq;
    }
}

// ---------------- K4: BN1 finalize + fc2 + [global barrier] + BN2 + tail -----
__global__ __launch_bounds__(256) void k_fc2tail(
    const float* __restrict__ cW2, const float* __restrict__ cb2,
    const float* __restrict__ g1,  const float* __restrict__ be1,
    const float* __restrict__ cW3, const float* __restrict__ cb3,
    const float* __restrict__ cW4, const float* __restrict__ cb4,
    const float* __restrict__ g2,  const float* __restrict__ be2,
    float* __restrict__ out, int B)
{
    __shared__ float w2s[512], b2s[16], bns[64];
    __shared__ float red1[4][64], tot1[64];
    __shared__ float wsum[8][32];
    __shared__ float w3s[128], b3s[8], w4s[8], bn2[32], tot2[32];
    int tid = threadIdx.x;

    {
        int c = tid & 63, rp = tid >> 6;
        int NB = B / 64;
        float sv = 0.f;
        for (int bb = rp; bb < NB; bb += 4) sv += g_part1[bb * 64 + c];
        red1[rp][c] = sv;
    }
    for (int i = tid; i < 512; i += 256) w2s[i] = cW2[i];
    if (tid < 128) w3s[tid] = cW3[tid];
    if (tid < 16)  b2s[tid] = cb2[tid];
    if (tid < 8) { b3s[tid] = cb3[tid]; w4s[tid] = cW4[tid]; }
    __syncthreads();
    if (tid < 64) tot1[tid] = red1[0][tid] + red1[1][tid] + red1[2][tid] + red1[3][tid];
    __syncthreads();
    if (tid < 32) {
        float invB  = 1.f / (float)B;
        float mean  = tot1[tid] * invB;
        float var   = tot1[32 + tid] * invB - mean * mean;
        float scale = g1[tid] * rsqrtf(var + 1e-5f);
        bns[tid]      = scale;
        bns[32 + tid] = be1[tid] - mean * scale;
    }
    __syncthreads();

    int sidx = blockIdx.x * 256 + tid;
    float z[32];
    const float4* yp = (const float4*)(g_y1 + (size_t)sidx * 32);
    #pragma unroll
    for (int i = 0; i < 8; i++) {
        float4 u = yp[i];
        z[4 * i + 0] = fmaxf(u.x * bns[4 * i + 0] + bns[32 + 4 * i + 0], 0.f);
        z[4 * i + 1] = fmaxf(u.y * bns[4 * i + 1] + bns[32 + 4 * i + 1], 0.f);
        z[4 * i + 2] = fmaxf(u.z * bns[4 * i + 2] + bns[32 + 4 * i + 2], 0.f);
        z[4 * i + 3] = fmaxf(u.w * bns[4 * i + 3] + bns[32 + 4 * i + 3], 0.f);
    }
    float y2v[16];
    #pragma unroll
    for (int j = 0; j < 16; j++) {
        float a = b2s[j];
        #pragma unroll
        for (int o = 0; o < 32; o++) a += z[o] * w2s[j * 32 + o];
        y2v[j] = a;
    }

    int lane = tid & 31, wp2 = tid >> 5;
    #pragma unroll
    for (int j = 0; j < 16; j++) {
        float su = y2v[j], sq = y2v[j] * y2v[j];
        #pragma unroll
        for (int o = 16; o; o >>= 1) {
            su += __shfl_xor_sync(0xffffffffu, su, o);
            sq += __shfl_xor_sync(0xffffffffu, sq, o);
        }
        if (lane == 0) { wsum[wp2][j] = su; wsum[wp2][16 + j] = sq; }
    }
    __syncthreads();
    if (tid < 32) {
        float sfull = 0.f;
        #pragma unroll
        for (int wi = 0; wi < 8; wi++) sfull += wsum[wi][tid];
        g_part2[blockIdx.x * 32 + tid] = sfull;
    }
    __syncthreads();

    if (tid == 0) {
        __threadfence();
        atomicAdd(&g_arrive, 1u);
        while (atomicAdd(&g_arrive, 0u) < gridDim.x) { }
        unsigned d = atomicAdd(&g_depart, 1u) + 1u;
        if (d == gridDim.x) {
            atomicExch(&g_arrive, 0u);
            atomicExch(&g_depart, 0u);
        }
    }
    __syncthreads();

    if (tid < 32) {
        float sv = 0.f;
        int NB2 = B / 256;
        for (int bb = 0; bb < NB2; bb++) sv += __ldcg(&g_part2[bb * 32 + tid]);
        tot2[tid] = sv;
    }
    __syncthreads();
    if (tid < 16) {
        float invB  = 1.f / (float)B;
        float mean  = tot2[tid] * invB;
        float var   = tot2[16 + tid] * invB - mean * mean;
        float scale = g2[tid] * rsqrtf(var + 1e-5f);
        bn2[tid]      = scale;
        bn2[16 + tid] = be2[tid] - mean * scale;
    }
    __syncthreads();

    float z2[16];
    #pragma unroll
    for (int j = 0; j < 16; j++)
        z2[j] = fmaxf(y2v[j] * bn2[j] + bn2[16 + j], 0.f);
    float o = cb4[0];
    #pragma unroll
    for (int j = 0; j < 8; j++) {
        float a = b3s[j];
        #pragma unroll
        for (int k = 0; k < 16; k++) a += z2[k] * w3s[j * 16 + k];
        o += fmaxf(a, 0.f) * w4s[j];
    }
    out[sidx] = 1.f / (1.f + expf(-o));
}

// ---------------- launch ------------------------------------------------------
extern "C" void kernel_launch(void* const* d_in, const int* in_sizes, int n_in,
                              void* d_out, int out_size) {
    const float* x    = (const float*)d_in[0];
    const float* qw   = (const float*)d_in[1];
    const float* aW   = (const float*)d_in[2];
    const float* ab   = (const float*)d_in[3];
    const float* fW1  = (const float*)d_in[4];
    const float* fb1  = (const float*)d_in[5];
    const float* fW2  = (const float*)d_in[6];
    const float* fb2  = (const float*)d_in[7];
    const float* cW1  = (const float*)d_in[8];
    const float* cb1  = (const float*)d_in[9];
    const float* g1   = (const float*)d_in[10];
    const float* be1  = (const float*)d_in[11];
    const float* cW2  = (const float*)d_in[12];
    const float* cb2  = (const float*)d_in[13];
    const float* g2   = (const float*)d_in[14];
    const float* be2  = (const float*)d_in[15];
    const float* cW3  = (const float*)d_in[16];
    const float* cb3  = (const float*)d_in[17];
    const float* cW4  = (const float*)d_in[18];
    const float* cb4  = (const float*)d_in[19];

    int B = in_sizes[0] / 256;
    int convB = B / 8;

    cudaFuncSetAttribute(k_feat, cudaFuncAttributeMaxDynamicSharedMemorySize, FEAT_SMEM);
    cudaFuncSetAttribute(k_gemm, cudaFuncAttributeMaxDynamicSharedMemorySize, GEMM_SMEM);

    k_prep<<<convB + 32, 256>>>(x, qw, convB);
    k_gemm<<<(B / 128) * 4, 256, GEMM_SMEM>>>(B);
    k_feat<<<B / 64, 256, FEAT_SMEM>>>(x, aW, ab, fW1, fb1, fW2, fb2, cW1, cb1, B);
    k_fc2tail<<<B / 256, 256>>>(cW2, cb2, g1, be1, cW3, cb3, cW4, cb4, g2, be2,
                                (float*)d_out, B);
}

// round 10
// speedup vs baseline: 1.4688x; 1.4688x over previous
#include <cuda_runtime.h>
#include <cuda_fp16.h>
#include <math.h>
#include <cstdint>

#define NQ 8
#define DIM 256
#define NL 6
#define MAXB 8192

typedef unsigned long long u64;

// ---------------- scratch ----------------
__device__ float  g_nrm2[MAXB];
__device__ __half g_xh[MAXB * 256];
__device__ __half g_Wh[512 * 256];          // row n=2j -> Re U[j,:], n=2j+1 -> Im U[j,:]
__device__ float4 g_eqp4[4 * MAXB];         // e partials per N-quarter
__device__ float  g_y1[MAXB * 32];
__device__ float  g_part1[(MAXB / 64) * 64];
__device__ float  g_part2[(MAXB / 256) * 32];
__device__ unsigned g_arrive;
__device__ unsigned g_depart;

// ---------------- helpers ----------------
__device__ __forceinline__ uint32_t smem_to_u32(const void* p) {
    uint32_t a;
    asm("{ .reg .u64 t; cvta.to.shared.u64 t, %1; cvt.u32.u64 %0, t; }" : "=r"(a) : "l"(p));
    return a;
}
#define SWZ(bo) ((bo) ^ (((bo) >> 3) & 0x70))

#define LDMX4(r, a) \
    asm volatile("ldmatrix.sync.aligned.m8n8.x4.shared.b16 {%0,%1,%2,%3}, [%4];" \
        : "=r"((r)[0]), "=r"((r)[1]), "=r"((r)[2]), "=r"((r)[3]) : "r"(a))
#define LDMX2(r, a) \
    asm volatile("ldmatrix.sync.aligned.m8n8.x2.shared.b16 {%0,%1}, [%2];" \
        : "=r"((r)[0]), "=r"((r)[1]) : "r"(a))
#define MMA_F16(d, a, b) \
    asm volatile("mma.sync.aligned.m16n8k16.row.col.f32.f16.f16.f32 " \
        "{%0,%1,%2,%3},{%4,%5,%6,%7},{%8,%9},{%0,%1,%2,%3};" \
        : "+f"((d)[0]), "+f"((d)[1]), "+f"((d)[2]), "+f"((d)[3]) \
        : "r"((a)[0]), "r"((a)[1]), "r"((a)[2]), "r"((a)[3]), "r"((b)[0]), "r"((b)[1]))
#define CP_ASYNC16(dst, src) \
    asm volatile("cp.async.cg.shared.global [%0], [%1], 16;" :: "r"(dst), "l"(src))
#define CP_COMMIT() asm volatile("cp.async.commit_group;" ::: "memory")
#define CP_WAIT(n)  asm volatile("cp.async.wait_group %0;" :: "n"(n) : "memory")

__device__ __forceinline__ float2 cmul(float2 a, float2 b) {
    return make_float2(a.x * b.x - a.y * b.y, a.x * b.y + a.y * b.x);
}
__device__ __forceinline__ float2 cadd(float2 a, float2 b) {
    return make_float2(a.x + b.x, a.y + b.y);
}
__device__ __forceinline__ u64 fma2(u64 a, u64 b, u64 c) {
    u64 d; asm("fma.rn.f32x2 %0,%1,%2,%3;" : "=l"(d) : "l"(a), "l"(b), "l"(c)); return d;
}
__device__ __forceinline__ u64 mul2(u64 a, u64 b) {
    u64 d; asm("mul.rn.f32x2 %0,%1,%2;" : "=l"(d) : "l"(a), "l"(b)); return d;
}
__device__ __forceinline__ u64 pack2(float lo, float hi) {
    u64 d; asm("mov.b64 %0,{%1,%2};" : "=l"(d) : "f"(lo), "f"(hi)); return d;
}
__device__ __forceinline__ float2 unpack2(u64 v) {
    float2 r; asm("mov.b64 {%0,%1},%2;" : "=f"(r.x), "=f"(r.y) : "l"(v)); return r;
}
__device__ __forceinline__ u64 splat2(float v) { return pack2(v, v); }
__device__ __forceinline__ u64 swap2(u64 v) { float2 r = unpack2(v); return pack2(r.y, r.x); }
__device__ __forceinline__ u64 shflxor2(u64 v, int m) { return __shfl_xor_sync(0xffffffffu, v, m); }

// ---------------- K1: prep — x->fp16 (blocks < convB) + basis sim (rest) -----
__global__ __launch_bounds__(256) void k_prep(const float* __restrict__ x,
                                              const float* __restrict__ qw, int convB) {
    __shared__ float2 gsh[NL * NQ * 4];
    __shared__ float  sre[8][256];
    __shared__ float  sim_[8][256];

    int t = threadIdx.x, w = t >> 5, l = t & 31;

    if ((int)blockIdx.x < convB) {
        int b = blockIdx.x * 8 + w;
        const float4* xp = (const float4*)(x + (size_t)b * 256 + l * 8);
        float4 v0 = xp[0], v1 = xp[1];
        float nr = v0.x*v0.x + v0.y*v0.y + v0.z*v0.z + v0.w*v0.w
                 + v1.x*v1.x + v1.y*v1.y + v1.z*v1.z + v1.w*v1.w;
        #pragma unroll
        for (int o = 16; o; o >>= 1) nr += __shfl_xor_sync(0xffffffffu, nr, o);
        if (l == 0) g_nrm2[b] = nr;
        float vv[8] = {v0.x, v0.y, v0.z, v0.w, v1.x, v1.y, v1.z, v1.w};
        unsigned hw[4];
        #pragma unroll
        for (int i = 0; i < 4; i++) {
            __half h0 = __float2half_rn(vv[2*i]);
            __half h1 = __float2half_rn(vv[2*i+1]);
            hw[i] = (unsigned)__half_as_ushort(h0) | ((unsigned)__half_as_ushort(h1) << 16);
        }
        *((uint4*)(g_xh + (size_t)b * 256 + l * 8)) = make_uint4(hw[0], hw[1], hw[2], hw[3]);
        return;
    }

    // basis sim: warp simulates basis state k -> column k of U (verified core)
    if (t < NL * NQ) {
        int lay = t >> 3, q = t & 7;
        float tx = 0.5f * qw[lay * 24 + q * 3 + 0];
        float ty = 0.5f * qw[lay * 24 + q * 3 + 1];
        float tz = 0.5f * qw[lay * 24 + q * 3 + 2];
        float cx = cosf(tx), sx = sinf(tx);
        float cy = cosf(ty), sy = sinf(ty);
        float cz = cosf(tz), sz = sinf(tz);
        float2 RX0 = make_float2(cx, 0.f), RX1 = make_float2(0.f, -sx);
        float2 RX2 = make_float2(0.f, -sx), RX3 = make_float2(cx, 0.f);
        float2 RY0 = make_float2(cy, 0.f), RY1 = make_float2(-sy, 0.f);
        float2 RY2 = make_float2(sy, 0.f), RY3 = make_float2(cy, 0.f);
        float2 RZ0 = make_float2(cz, -sz), RZ3 = make_float2(cz, sz);
        float2 M0 = cadd(cmul(RY0, RX0), cmul(RY1, RX2));
        float2 M1 = cadd(cmul(RY0, RX1), cmul(RY1, RX3));
        float2 M2 = cadd(cmul(RY2, RX0), cmul(RY3, RX2));
        float2 M3 = cadd(cmul(RY2, RX1), cmul(RY3, RX3));
        gsh[t * 4 + 0] = cmul(RZ0, M0);
        gsh[t * 4 + 1] = cmul(RZ0, M1);
        gsh[t * 4 + 2] = cmul(RZ3, M2);
        gsh[t * 4 + 3] = cmul(RZ3, M3);
    }

    int k = (blockIdx.x - convB) * 8 + w;

    u64 xv[4], yv[4];
    #pragma unroll
    for (int v = 0; v < 4; v++) {
        float a0 = (l == (k >> 3) && (k & 7) == 2 * v)     ? 1.f : 0.f;
        float a1 = (l == (k >> 3) && (k & 7) == 2 * v + 1) ? 1.f : 0.f;
        xv[v] = pack2(a0, a1);
        yv[v] = 0ull;
    }

    const int cbs[11] = {3, 5, 7, 0, 1, 2, 3, 4, 5, 6, 7};
    const int tbs[11] = {1, 3, 5, 7, 0, 1, 2, 3, 4, 5, 6};
    int rslot[8];
    #pragma unroll
    for (int jj = 0; jj < 8; jj++) {
        int p = l * 8 + jj;
        #pragma unroll
        for (int gi = 0; gi < 11; gi++)
            p ^= ((p >> cbs[gi]) & 1) << tbs[gi];
        rslot[jj] = ((p & 7) << 5) | (p >> 3);
    }

    __syncthreads();

    for (int lay = 0; lay < NL; lay++) {
        #pragma unroll
        for (int q = 0; q < NQ; q++) {
            const int bp = 7 - q;
            const float2* U = &gsh[(lay * 8 + q) * 4];
            float2 u0 = U[0], u1 = U[1], u2 = U[2], u3 = U[3];
            if (bp >= 3) {
                int msk = 1 << (bp - 3);
                int myb = (l >> (bp - 3)) & 1;
                float2 uA = myb ? u3 : u0;
                float2 uB = myb ? u2 : u1;
                u64 uAx = splat2(uA.x), uAy = splat2(uA.y), nuAy = splat2(-uA.y);
                u64 uBx = splat2(uB.x), uBy = splat2(uB.y), nuBy = splat2(-uB.y);
                #pragma unroll
                for (int v = 0; v < 4; v++) {
                    u64 px = shflxor2(xv[v], msk);
                    u64 py = shflxor2(yv[v], msk);
                    u64 nx = fma2(uAx, xv[v], fma2(nuAy, yv[v], fma2(uBx, px, mul2(nuBy, py))));
                    u64 ny = fma2(uAx, yv[v], fma2(uAy, xv[v], fma2(uBx, py, mul2(uBy, px))));
                    xv[v] = nx; yv[v] = ny;
                }
            } else if (bp >= 1) {
                u64 u0x = splat2(u0.x), u0y = splat2(u0.y), nu0y = splat2(-u0.y);
                u64 u1x = splat2(u1.x), u1y = splat2(u1.y), nu1y = splat2(-u1.y);
                u64 u2x = splat2(u2.x), u2y = splat2(u2.y), nu2y = splat2(-u2.y);
                u64 u3x = splat2(u3.x), u3y = splat2(u3.y), nu3y = splat2(-u3.y);
                #pragma unroll
                for (int pr = 0; pr < 2; pr++) {
                    int a = (bp == 1) ? (pr * 2) : pr;
                    int c = (bp == 1) ? (pr * 2 + 1) : (pr + 2);
                    u64 ax = xv[a], ay = yv[a], bx = xv[c], by = yv[c];
                    xv[a] = fma2(u0x, ax, fma2(nu0y, ay, fma2(u1x, bx, mul2(nu1y, by))));
                    yv[a] = fma2(u0x, ay, fma2(u0y, ax, fma2(u1x, by, mul2(u1y, bx))));
                    xv[c] = fma2(u2x, ax, fma2(nu2y, ay, fma2(u3x, bx, mul2(nu3y, by))));
                    yv[c] = fma2(u2x, ay, fma2(u2y, ax, fma2(u3x, by, mul2(u3y, bx))));
                }
            } else {
                u64 Ax = pack2(u0.x, u3.x), Ay = pack2(u0.y, u3.y), nAy = pack2(-u0.y, -u3.y);
                u64 Bx = pack2(u1.x, u2.x), By = pack2(u1.y, u2.y), nBy = pack2(-u1.y, -u2.y);
                #pragma unroll
                for (int v = 0; v < 4; v++) {
                    u64 xs_ = swap2(xv[v]);
                    u64 ys_ = swap2(yv[v]);
                    u64 nx = fma2(Ax, xv[v], fma2(nAy, yv[v], fma2(Bx, xs_, mul2(nBy, ys_))));
                    u64 ny = fma2(Ax, yv[v], fma2(Ay, xv[v], fma2(Bx, ys_, mul2(By, xs_))));
                    xv[v] = nx; yv[v] = ny;
                }
            }
        }
        __syncwarp();
        #pragma unroll
        for (int v = 0; v < 4; v++) {
            float2 rx = unpack2(xv[v]), ry = unpack2(yv[v]);
            sre[w][(2 * v) * 32 + l]      = rx.x;
            sre[w][(2 * v + 1) * 32 + l]  = rx.y;
            sim_[w][(2 * v) * 32 + l]     = ry.x;
            sim_[w][(2 * v + 1) * 32 + l] = ry.y;
        }
        __syncwarp();
        #pragma unroll
        for (int v = 0; v < 4; v++) {
            xv[v] = pack2(sre[w][rslot[2 * v]], sre[w][rslot[2 * v + 1]]);
            yv[v] = pack2(sim_[w][rslot[2 * v]], sim_[w][rslot[2 * v + 1]]);
        }
    }

    #pragma unroll
    for (int v = 0; v < 4; v++) {
        float2 rx = unpack2(xv[v]), ry = unpack2(yv[v]);
        int j0 = 8 * l + 2 * v;
        float vals[4] = {rx.x, ry.x, rx.y, ry.y};
        #pragma unroll
        for (int r = 0; r < 4; r++)
            g_Wh[(size_t)(2 * j0 + r) * 256 + k] = __float2half_rn(vals[r]);
    }
}

// ---------------- K2: fp16 mma.sync GEMM (W x) + expectation epilogue --------
// CTA: 128 samples x 128 W-rows (nb quarter), K=256, 2-stage cp.async pipeline.
#define GEMM_SMEM 65536   // 2 stages x (A 16KB + B 16KB)

__global__ __launch_bounds__(256) void k_gemm(int B) {
    extern __shared__ __align__(16) char smg[];
    uint32_t sb = smem_to_u32(smg);
    int tid = threadIdx.x;
    int w = tid >> 5, l = tid & 31;
    int tile = blockIdx.x >> 2, nb = blockIdx.x & 3;
    int S0 = tile * 128;

    int r8 = l & 7, grp = l >> 3;
    int rowA = r8 + ((grp & 1) << 3);
    int colA = (grp & 2) << 3;
    int rowB = l & 7;
    int colB = ((l >> 3) & 1) << 4;

    float acc[8][2][4];
    #pragma unroll
    for (int mt = 0; mt < 8; mt++)
        #pragma unroll
        for (int nt = 0; nt < 2; nt++)
            #pragma unroll
            for (int c = 0; c < 4; c++) acc[mt][nt][c] = 0.f;

    // stage loader: A at st*32768, B at st*32768+16384
    #define LOAD_STAGE(kc, st) do { \
        int base_ = (st) * 32768; \
        for (int i = tid; i < 1024; i += 256) { \
            int row_ = i >> 3, seg_ = i & 7; \
            uint32_t dst_ = SWZ((uint32_t)(row_ * 128 + seg_ * 16)); \
            const __half* sA_ = g_xh + (size_t)(S0 + row_) * 256 + (kc) * 64 + seg_ * 8; \
            const __half* sB_ = g_Wh + (size_t)(nb * 128 + row_) * 256 + (kc) * 64 + seg_ * 8; \
            CP_ASYNC16(sb + base_ + dst_, sA_); \
            CP_ASYNC16(sb + base_ + 16384 + dst_, sB_); \
        } \
        CP_COMMIT(); \
    } while (0)

    LOAD_STAGE(0, 0);
    for (int kc = 0; kc < 4; kc++) {
        if (kc < 3) { LOAD_STAGE(kc + 1, (kc + 1) & 1); CP_WAIT(1); }
        else        { CP_WAIT(0); }
        __syncthreads();
        uint32_t base = sb + (kc & 1) * 32768;
        #pragma unroll
        for (int ks = 0; ks < 4; ks++) {
            uint32_t bh[2][2];
            #pragma unroll
            for (int nt = 0; nt < 2; nt++) {
                uint32_t boff = SWZ((uint32_t)((w * 16 + nt * 8 + rowB) * 128 + ks * 32 + colB));
                LDMX2(bh[nt], base + 16384 + boff);
            }
            #pragma unroll
            for (int mt = 0; mt < 8; mt++) {
                uint32_t aoff = SWZ((uint32_t)((mt * 16 + rowA) * 128 + ks * 32 + colA));
                uint32_t ah[4];
                LDMX4(ah, base + aoff);
                #pragma unroll
                for (int nt = 0; nt < 2; nt++)
                    MMA_F16(acc[mt][nt], ah, bh[nt]);
            }
        }
        __syncthreads();
    }

    // epilogue (verified R9): P = re^2 + im^2 per lane, signed reductions
    float* e_s = (float*)smg;   // [8 warps][128 m][4] = 16KB
    #pragma unroll
    for (int mt = 0; mt < 8; mt++) {
        float sa0 = 0.f, sa1 = 0.f, sa2 = 0.f, sa3 = 0.f;
        float sb0 = 0.f, sb1 = 0.f, sb2 = 0.f, sb3 = 0.f;
        #pragma unroll
        for (int nt = 0; nt < 2; nt++) {
            float c0 = acc[mt][nt][0], c1 = acc[mt][nt][1];
            float c2 = acc[mt][nt][2], c3 = acc[mt][nt][3];
            float Pa = c0 * c0 + c1 * c1;
            float Pb = c2 * c2 + c3 * c3;
            int j = nb * 64 + w * 8 + nt * 4 + (l & 3);
            float f0 = (j & 128) ? -1.f : 1.f;
            float f1 = (j & 64)  ? -1.f : 1.f;
            float f2 = (j & 32)  ? -1.f : 1.f;
            float f3 = (j & 16)  ? -1.f : 1.f;
            sa0 += f0 * Pa; sa1 += f1 * Pa; sa2 += f2 * Pa; sa3 += f3 * Pa;
            sb0 += f0 * Pb; sb1 += f1 * Pb; sb2 += f2 * Pb; sb3 += f3 * Pb;
        }
        #define REDL(v) { v += __shfl_xor_sync(0xffffffffu, v, 1); v += __shfl_xor_sync(0xffffffffu, v, 2); }
        REDL(sa0) REDL(sa1) REDL(sa2) REDL(sa3)
        REDL(sb0) REDL(sb1) REDL(sb2) REDL(sb3)
        if ((l & 3) == 0) {
            int m1 = mt * 16 + (l >> 2);
            float* p1 = e_s + (w * 128 + m1) * 4;
            p1[0] = sa0; p1[1] = sa1; p1[2] = sa2; p1[3] = sa3;
            float* p2 = e_s + (w * 128 + m1 + 8) * 4;
            p2[0] = sb0; p2[1] = sb1; p2[2] = sb2; p2[3] = sb3;
        }
    }
    __syncthreads();
    if (tid < 128) {
        float4 r = make_float4(0.f, 0.f, 0.f, 0.f);
        #pragma unroll
        for (int w8 = 0; w8 < 8; w8++) {
            const float* p = e_s + (w8 * 128 + tid) * 4;
            r.x += p[0]; r.y += p[1]; r.z += p[2]; r.w += p[3];
        }
        g_eqp4[nb * MAXB + S0 + tid] = r;
    }
}

// ---------------- K3: feature processor + adapter + fc1 + BN1 partials -------
#define FEAT_SMEM (64*260*4 + 64*68*4 + 2048)

__global__ __launch_bounds__(256, 2) void k_feat(
    const float* __restrict__ x,
    const float* __restrict__ aW, const float* __restrict__ ab,
    const float* __restrict__ fW1, const float* __restrict__ fb1,
    const float* __restrict__ fW2, const float* __restrict__ fb2,
    const float* __restrict__ cW1, const float* __restrict__ cb1, int B)
{
    extern __shared__ __align__(16) char sm[];
    float (*xs)[260] = (float(*)[260])sm;
    float (*ws)[68]  = (float(*)[68])(sm + 66560);
    float *cst       = (float*)(sm + 83968);
    float *fw2s = cst;
    float *cw1s = cst + 256;
    float *fb1s = cst + 384;
    float *cb1s = cst + 448;
    float *fb2s = cst + 480;
    float *abs_ = cst + 484;
    float *aWs  = cst + 488;
    float (*h1s)[68] = (float(*)[68])sm;
    float (*hs)[8]   = (float(*)[8])(sm + 20480);
    float (*ys)[33]  = (float(*)[33])(sm + 24576);

    int tid = threadIdx.x;
    int S0 = blockIdx.x * 64;
    int w = tid >> 5, l = tid & 31;

    fw2s[tid] = fW2[tid];
    if (tid < 128) cw1s[tid] = cW1[tid];
    if (tid < 64)  fb1s[tid] = fb1[tid];
    if (tid < 32)  cb1s[tid] = cb1[tid];
    if (tid < 16)  aWs[tid]  = aW[tid];
    if (tid < 4) { fb2s[tid] = fb2[tid]; abs_[tid] = ab[tid]; }

    for (int i = tid; i < 64 * 64; i += 256) {
        int s = i >> 6, q = i & 63;
        ((float4*)&xs[s][0])[q] = ((const float4*)(x + (size_t)(S0 + s) * 256))[q];
    }

    u64 acc[2][8];
    #pragma unroll
    for (int sg = 0; sg < 2; sg++)
        #pragma unroll
        for (int j = 0; j < 8; j++) acc[sg][j] = 0ull;

    for (int kc = 0; kc < 4; kc++) {
        __syncthreads();
        for (int i = tid; i < 64 * 16; i += 256) {
            int o = i >> 4, q = i & 15;
            ((float4*)&ws[o][0])[q] = ((const float4*)(fW1 + o * 256 + kc * 64))[q];
        }
        __syncthreads();
        const float4* xr0 = (const float4*)&xs[l][kc * 64];
        const float4* xr1 = (const float4*)&xs[l + 32][kc * 64];
        #pragma unroll
        for (int q = 0; q < 16; q++) {
            float4 a4 = xr0[q], b4 = xr1[q];
            u64 x0lo = pack2(a4.x, a4.y), x0hi = pack2(a4.z, a4.w);
            u64 x1lo = pack2(b4.x, b4.y), x1hi = pack2(b4.z, b4.w);
            #pragma unroll
            for (int j = 0; j < 8; j++) {
                float4 w4 = ((const float4*)&ws[w * 8 + j][0])[q];
                u64 wlo = pack2(w4.x, w4.y), whi = pack2(w4.z, w4.w);
                acc[0][j] = fma2(wlo, x0lo, acc[0][j]);
                acc[0][j] = fma2(whi, x0hi, acc[0][j]);
                acc[1][j] = fma2(wlo, x1lo, acc[1][j]);
                acc[1][j] = fma2(whi, x1hi, acc[1][j]);
            }
        }
    }
    __syncthreads();

    #pragma unroll
    for (int sg = 0; sg < 2; sg++) {
        int s = l + 32 * sg;
        #pragma unroll
        for (int j = 0; j < 8; j++) {
            float2 r = unpack2(acc[sg][j]);
            h1s[s][w * 8 + j] = fmaxf(r.x + r.y + fb1s[w * 8 + j], 0.f);
        }
    }
    __syncthreads();

    {
        int s = tid & 63, j = tid >> 6;
        float a = fb2s[j];
        const float4* hp = (const float4*)&h1s[s][0];
        const float4* wp = (const float4*)&fw2s[j * 64];
        #pragma unroll
        for (int q = 0; q < 16; q++) {
            float4 h = hp[q], wv = wp[q];
            a += h.x * wv.x + h.y * wv.y + h.z * wv.z + h.w * wv.w;
        }
        float cf = tanhf(a);
        float4 q0 = g_eqp4[0 * MAXB + S0 + s];
        float4 q1 = g_eqp4[1 * MAXB + S0 + s];
        float4 q2 = g_eqp4[2 * MAXB + S0 + s];
        float4 q3 = g_eqp4[3 * MAXB + S0 + s];
        float inv = 1.f / g_nrm2[S0 + s];
        float qx = (q0.x + q1.x + q2.x + q3.x) * inv;
        float qy = (q0.y + q1.y + q2.y + q3.y) * inv;
        float qz = (q0.z + q1.z + q2.z + q3.z) * inv;
        float qw = (q0.w + q1.w + q2.w + q3.w) * inv;
        float qf = abs_[j] + aWs[j * 4 + 0] * qx + aWs[j * 4 + 1] * qy
                           + aWs[j * 4 + 2] * qz + aWs[j * 4 + 3] * qw;
        hs[s][j] = cf + qf;
    }
    __syncthreads();

    for (int i = tid; i < 64 * 32; i += 256) {
        int s = i >> 5, o = i & 31;
        float vv = cb1s[o];
        #pragma unroll
        for (int k = 0; k < 4; k++) vv += hs[s][k] * cw1s[o * 4 + k];
        g_y1[(size_t)(S0 + s) * 32 + o] = vv;
        ys[s][o] = vv;
    }
    __syncthreads();

    if (tid < 32) {
        float su = 0.f, sq = 0.f;
        #pragma unroll
        for (int s = 0; s < 64; s++) {
            float vv = ys[s][tid];
            su += vv; sq += vv * vv;
        }
        g_part1[blockIdx.x * 64 + tid]      = su;
        g_part1[blockIdx.x * 64 + 32 + tid] = sq;
    }
}

// ---------------- K4: BN1 finalize + fc2 + [global barrier] + BN2 + tail -----
__global__ __launch_bounds__(256) void k_fc2tail(
    const float* __restrict__ cW2, const float* __restrict__ cb2,
    const float* __restrict__ g1,  const float* __restrict__ be1,
    const float* __restrict__ cW3, const float* __restrict__ cb3,
    const float* __restrict__ cW4, const float* __restrict__ cb4,
    const float* __restrict__ g2,  const float* __restrict__ be2,
    float* __restrict__ out, int B)
{
    __shared__ float w2s[512], b2s[16], bns[64];
    __shared__ float red1[4][64], tot1[64];
    __shared__ float wsum[8][32];
    __shared__ float w3s[128], b3s[8], w4s[8], bn2[32], tot2[32];
    int tid = threadIdx.x;
    int sidx = blockIdx.x * 256 + tid;

    // prefetch y1 early (independent of the reductions below)
    float4 u4[8];
    const float4* yp = (const float4*)(g_y1 + (size_t)sidx * 32);
    #pragma unroll
    for (int i = 0; i < 8; i++) u4[i] = yp[i];

    {
        int c = tid & 63, rp = tid >> 6;
        int NB = B / 64;
        float sv = 0.f;
        for (int bb = rp; bb < NB; bb += 4) sv += g_part1[bb * 64 + c];
        red1[rp][c] = sv;
    }
    for (int i = tid; i < 512; i += 256) w2s[i] = cW2[i];
    if (tid < 128) w3s[tid] = cW3[tid];
    if (tid < 16)  b2s[tid] = cb2[tid];
    if (tid < 8) { b3s[tid] = cb3[tid]; w4s[tid] = cW4[tid]; }
    __syncthreads();
    if (tid < 64) tot1[tid] = red1[0][tid] + red1[1][tid] + red1[2][tid] + red1[3][tid];
    __syncthreads();
    if (tid < 32) {
        float invB  = 1.f / (float)B;
        float mean  = tot1[tid] * invB;
        float var   = tot1[32 + tid] * invB - mean * mean;
        float scale = g1[tid] * rsqrtf(var + 1e-5f);
        bns[tid]      = scale;
        bns[32 + tid] = be1[tid] - mean * scale;
    }
    __syncthreads();

    float z[32];
    #pragma unroll
    for (int i = 0; i < 8; i++) {
        z[4 * i + 0] = fmaxf(u4[i].x * bns[4 * i + 0] + bns[32 + 4 * i + 0], 0.f);
        z[4 * i + 1] = fmaxf(u4[i].y * bns[4 * i + 1] + bns[32 + 4 * i + 1], 0.f);
        z[4 * i + 2] = fmaxf(u4[i].z * bns[4 * i + 2] + bns[32 + 4 * i + 2], 0.f);
        z[4 * i + 3] = fmaxf(u4[i].w * bns[4 * i + 3] + bns[32 + 4 * i + 3], 0.f);
    }
    float y2v[16];
    #pragma unroll
    for (int j = 0; j < 16; j++) {
        float a = b2s[j];
        #pragma unroll
        for (int o = 0; o < 32; o++) a += z[o] * w2s[j * 32 + o];
        y2v[j] = a;
    }

    int lane = tid & 31, wp2 = tid >> 5;
    #pragma unroll
    for (int j = 0; j < 16; j++) {
        float su = y2v[j], sq = y2v[j] * y2v[j];
        #pragma unroll
        for (int o = 16; o; o >>= 1) {
            su += __shfl_xor_sync(0xffffffffu, su, o);
            sq += __shfl_xor_sync(0xffffffffu, sq, o);
        }
        if (lane == 0) { wsum[wp2][j] = su; wsum[wp2][16 + j] = sq; }
    }
    __syncthreads();
    if (tid < 32) {
        float sfull = 0.f;
        #pragma unroll
        for (int wi = 0; wi < 8; wi++) sfull += wsum[wi][tid];
        g_part2[blockIdx.x * 32 + tid] = sfull;
    }
    __syncthreads();

    if (tid == 0) {
        __threadfence();
        atomicAdd(&g_arrive, 1u);
        while (atomicAdd(&g_arrive, 0u) < gridDim.x) { }
        unsigned d = atomicAdd(&g_depart, 1u) + 1u;
        if (d == gridDim.x) {
            atomicExch(&g_arrive, 0u);
            atomicExch(&g_depart, 0u);
        }
    }
    __syncthreads();

    if (tid < 32) {
        float sv = 0.f;
        int NB2 = B / 256;
        for (int bb = 0; bb < NB2; bb++) sv += __ldcg(&g_part2[bb * 32 + tid]);
        tot2[tid] = sv;
    }
    __syncthreads();
    if (tid < 16) {
        float invB  = 1.f / (float)B;
        float mean  = tot2[tid] * invB;
        float var   = tot2[16 + tid] * invB - mean * mean;
        float scale = g2[tid] * rsqrtf(var + 1e-5f);
        bn2[tid]      = scale;
        bn2[16 + tid] = be2[tid] - mean * scale;
    }
    __syncthreads();

    float z2[16];
    #pragma unroll
    for (int j = 0; j < 16; j++)
        z2[j] = fmaxf(y2v[j] * bn2[j] + bn2[16 + j], 0.f);
    float o = cb4[0];
    #pragma unroll
    for (int j = 0; j < 8; j++) {
        float a = b3s[j];
        #pragma unroll
        for (int k = 0; k < 16; k++) a += z2[k] * w3s[j * 16 + k];
        o += fmaxf(a, 0.f) * w4s[j];
    }
    out[sidx] = 1.f / (1.f + expf(-o));
}

// ---------------- launch ------------------------------------------------------
extern "C" void kernel_launch(void* const* d_in, const int* in_sizes, int n_in,
                              void* d_out, int out_size) {
    const float* x    = (const float*)d_in[0];
    const float* qw   = (const float*)d_in[1];
    const float* aW   = (const float*)d_in[2];
    const float* ab   = (const float*)d_in[3];
    const float* fW1  = (const float*)d_in[4];
    const float* fb1  = (const float*)d_in[5];
    const float* fW2  = (const float*)d_in[6];
    const float* fb2  = (const float*)d_in[7];
    const float* cW1  = (const float*)d_in[8];
    const float* cb1  = (const float*)d_in[9];
    const float* g1   = (const float*)d_in[10];
    const float* be1  = (const float*)d_in[11];
    const float* cW2  = (const float*)d_in[12];
    const float* cb2  = (const float*)d_in[13];
    const float* g2   = (const float*)d_in[14];
    const float* be2  = (const float*)d_in[15];
    const float* cW3  = (const float*)d_in[16];
    const float* cb3  = (const float*)d_in[17];
    const float* cW4  = (const float*)d_in[18];
    const float* cb4  = (const float*)d_in[19];

    int B = in_sizes[0] / 256;
    int convB = B / 8;

    cudaFuncSetAttribute(k_feat, cudaFuncAttributeMaxDynamicSharedMemorySize, FEAT_SMEM);
    cudaFuncSetAttribute(k_gemm, cudaFuncAttributeMaxDynamicSharedMemorySize, GEMM_SMEM);

    k_prep<<<convB + 32, 256>>>(x, qw, convB);
    k_gemm<<<(B / 128) * 4, 256, GEMM_SMEM>>>(B);
    k_feat<<<B / 64, 256, FEAT_SMEM>>>(x, aW, ab, fW1, fb1, fW2, fb2, cW1, cb1, B);
    k_fc2tail<<<B / 256, 256>>>(cW2, cb2, g1, be1, cW3, cb3, cW4, cb4, g2, be2,
                                (float*)d_out, B);
}

// round 13
// speedup vs baseline: 1.5077x; 1.0265x over previous
#include <cuda_runtime.h>
#include <cuda_fp16.h>
#include <math.h>
#include <cstdint>

#define NQ 8
#define DIM 256
#define NL 6
#define MAXB 8192

typedef unsigned long long u64;

// ---------------- scratch ----------------
__device__ float  g_nrm2[MAXB];
__device__ __half g_xh[MAXB * 256];
__device__ __half g_Wh[512 * 256];          // row n=2j -> Re U[j,:], n=2j+1 -> Im U[j,:]
__device__ float4 g_eqp4[4 * MAXB];         // e partials per N-quarter
__device__ float  g_part1[(MAXB / 64) * 64];
__device__ float  g_part2[(MAXB / 64) * 32];
__device__ unsigned g_arr1, g_dep1, g_arr2, g_dep2;

// ---------------- helpers ----------------
__device__ __forceinline__ uint32_t smem_to_u32(const void* p) {
    uint32_t a;
    asm("{ .reg .u64 t; cvta.to.shared.u64 t, %1; cvt.u32.u64 %0, t; }" : "=r"(a) : "l"(p));
    return a;
}
#define SWZ(bo) ((bo) ^ (((bo) >> 3) & 0x70))

#define LDMX4(r, a) \
    asm volatile("ldmatrix.sync.aligned.m8n8.x4.shared.b16 {%0,%1,%2,%3}, [%4];" \
        : "=r"((r)[0]), "=r"((r)[1]), "=r"((r)[2]), "=r"((r)[3]) : "r"(a))
#define LDMX2(r, a) \
    asm volatile("ldmatrix.sync.aligned.m8n8.x2.shared.b16 {%0,%1}, [%2];" \
        : "=r"((r)[0]), "=r"((r)[1]) : "r"(a))
#define MMA_F16(d, a, b) \
    asm volatile("mma.sync.aligned.m16n8k16.row.col.f32.f16.f16.f32 " \
        "{%0,%1,%2,%3},{%4,%5,%6,%7},{%8,%9},{%0,%1,%2,%3};" \
        : "+f"((d)[0]), "+f"((d)[1]), "+f"((d)[2]), "+f"((d)[3]) \
        : "r"((a)[0]), "r"((a)[1]), "r"((a)[2]), "r"((a)[3]), "r"((b)[0]), "r"((b)[1]))
#define CP_ASYNC16(dst, src) \
    asm volatile("cp.async.cg.shared.global [%0], [%1], 16;" :: "r"(dst), "l"(src))
#define CP_COMMIT() asm volatile("cp.async.commit_group;" ::: "memory")
#define CP_WAIT(n)  asm volatile("cp.async.wait_group %0;" :: "n"(n) : "memory")

// self-resetting device-wide barrier (R4-proven pattern)
#define GLOBAL_BARRIER(arr, dep) do { \
    if (threadIdx.x == 0) { \
        __threadfence(); \
        atomicAdd(&(arr), 1u); \
        while (atomicAdd(&(arr), 0u) < gridDim.x) { } \
        unsigned d_ = atomicAdd(&(dep), 1u) + 1u; \
        if (d_ == gridDim.x) { atomicExch(&(arr), 0u); atomicExch(&(dep), 0u); } \
    } \
    __syncthreads(); \
} while (0)

__device__ __forceinline__ float2 cmul(float2 a, float2 b) {
    return make_float2(a.x * b.x - a.y * b.y, a.x * b.y + a.y * b.x);
}
__device__ __forceinline__ float2 cadd(float2 a, float2 b) {
    return make_float2(a.x + b.x, a.y + b.y);
}
__device__ __forceinline__ u64 fma2(u64 a, u64 b, u64 c) {
    u64 d; asm("fma.rn.f32x2 %0,%1,%2,%3;" : "=l"(d) : "l"(a), "l"(b), "l"(c)); return d;
}
__device__ __forceinline__ u64 mul2(u64 a, u64 b) {
    u64 d; asm("mul.rn.f32x2 %0,%1,%2;" : "=l"(d) : "l"(a), "l"(b)); return d;
}
__device__ __forceinline__ u64 pack2(float lo, float hi) {
    u64 d; asm("mov.b64 %0,{%1,%2};" : "=l"(d) : "f"(lo), "f"(hi)); return d;
}
__device__ __forceinline__ float2 unpack2(u64 v) {
    float2 r; asm("mov.b64 {%0,%1},%2;" : "=f"(r.x), "=f"(r.y) : "l"(v)); return r;
}
__device__ __forceinline__ u64 splat2(float v) { return pack2(v, v); }
__device__ __forceinline__ u64 swap2(u64 v) { float2 r = unpack2(v); return pack2(r.y, r.x); }
__device__ __forceinline__ u64 shflxor2(u64 v, int m) { return __shfl_xor_sync(0xffffffffu, v, m); }

// ---------------- K1: prep — x->fp16 (blocks < convB) + basis sim (rest) -----
__global__ __launch_bounds__(256) void k_prep(const float* __restrict__ x,
                                              const float* __restrict__ qw, int convB) {
    __shared__ float2 gsh[NL * NQ * 4];
    __shared__ float  sre[8][256];
    __shared__ float  sim_[8][256];

    int t = threadIdx.x, w = t >> 5, l = t & 31;

    if ((int)blockIdx.x < convB) {
        int b = blockIdx.x * 8 + w;
        const float4* xp = (const float4*)(x + (size_t)b * 256 + l * 8);
        float4 v0 = xp[0], v1 = xp[1];
        float nr = v0.x*v0.x + v0.y*v0.y + v0.z*v0.z + v0.w*v0.w
                 + v1.x*v1.x + v1.y*v1.y + v1.z*v1.z + v1.w*v1.w;
        #pragma unroll
        for (int o = 16; o; o >>= 1) nr += __shfl_xor_sync(0xffffffffu, nr, o);
        if (l == 0) g_nrm2[b] = nr;
        float vv[8] = {v0.x, v0.y, v0.z, v0.w, v1.x, v1.y, v1.z, v1.w};
        unsigned hw[4];
        #pragma unroll
        for (int i = 0; i < 4; i++) {
            __half h0 = __float2half_rn(vv[2*i]);
            __half h1 = __float2half_rn(vv[2*i+1]);
            hw[i] = (unsigned)__half_as_ushort(h0) | ((unsigned)__half_as_ushort(h1) << 16);
        }
        *((uint4*)(g_xh + (size_t)b * 256 + l * 8)) = make_uint4(hw[0], hw[1], hw[2], hw[3]);
        return;
    }

    if (t < NL * NQ) {
        int lay = t >> 3, q = t & 7;
        float tx = 0.5f * qw[lay * 24 + q * 3 + 0];
        float ty = 0.5f * qw[lay * 24 + q * 3 + 1];
        float tz = 0.5f * qw[lay * 24 + q * 3 + 2];
        float cx = cosf(tx), sx = sinf(tx);
        float cy = cosf(ty), sy = sinf(ty);
        float cz = cosf(tz), sz = sinf(tz);
        float2 RX0 = make_float2(cx, 0.f), RX1 = make_float2(0.f, -sx);
        float2 RX2 = make_float2(0.f, -sx), RX3 = make_float2(cx, 0.f);
        float2 RY0 = make_float2(cy, 0.f), RY1 = make_float2(-sy, 0.f);
        float2 RY2 = make_float2(sy, 0.f), RY3 = make_float2(cy, 0.f);
        float2 RZ0 = make_float2(cz, -sz), RZ3 = make_float2(cz, sz);
        float2 M0 = cadd(cmul(RY0, RX0), cmul(RY1, RX2));
        float2 M1 = cadd(cmul(RY0, RX1), cmul(RY1, RX3));
        float2 M2 = cadd(cmul(RY2, RX0), cmul(RY3, RX2));
        float2 M3 = cadd(cmul(RY2, RX1), cmul(RY3, RX3));
        gsh[t * 4 + 0] = cmul(RZ0, M0);
        gsh[t * 4 + 1] = cmul(RZ0, M1);
        gsh[t * 4 + 2] = cmul(RZ3, M2);
        gsh[t * 4 + 3] = cmul(RZ3, M3);
    }

    int k = (blockIdx.x - convB) * 8 + w;

    u64 xv[4], yv[4];
    #pragma unroll
    for (int v = 0; v < 4; v++) {
        float a0 = (l == (k >> 3) && (k & 7) == 2 * v)     ? 1.f : 0.f;
        float a1 = (l == (k >> 3) && (k & 7) == 2 * v + 1) ? 1.f : 0.f;
        xv[v] = pack2(a0, a1);
        yv[v] = 0ull;
    }

    const int cbs[11] = {3, 5, 7, 0, 1, 2, 3, 4, 5, 6, 7};
    const int tbs[11] = {1, 3, 5, 7, 0, 1, 2, 3, 4, 5, 6};
    int rslot[8];
    #pragma unroll
    for (int jj = 0; jj < 8; jj++) {
        int p = l * 8 + jj;
        #pragma unroll
        for (int gi = 0; gi < 11; gi++)
            p ^= ((p >> cbs[gi]) & 1) << tbs[gi];
        rslot[jj] = ((p & 7) << 5) | (p >> 3);
    }

    __syncthreads();

    for (int lay = 0; lay < NL; lay++) {
        #pragma unroll
        for (int q = 0; q < NQ; q++) {
            const int bp = 7 - q;
            const float2* U = &gsh[(lay * 8 + q) * 4];
            float2 u0 = U[0], u1 = U[1], u2 = U[2], u3 = U[3];
            if (bp >= 3) {
                int msk = 1 << (bp - 3);
                int myb = (l >> (bp - 3)) & 1;
                float2 uA = myb ? u3 : u0;
                float2 uB = myb ? u2 : u1;
                u64 uAx = splat2(uA.x), uAy = splat2(uA.y), nuAy = splat2(-uA.y);
                u64 uBx = splat2(uB.x), uBy = splat2(uB.y), nuBy = splat2(-uB.y);
                #pragma unroll
                for (int v = 0; v < 4; v++) {
                    u64 px = shflxor2(xv[v], msk);
                    u64 py = shflxor2(yv[v], msk);
                    u64 nx = fma2(uAx, xv[v], fma2(nuAy, yv[v], fma2(uBx, px, mul2(nuBy, py))));
                    u64 ny = fma2(uAx, yv[v], fma2(uAy, xv[v], fma2(uBx, py, mul2(uBy, px))));
                    xv[v] = nx; yv[v] = ny;
                }
            } else if (bp >= 1) {
                u64 u0x = splat2(u0.x), u0y = splat2(u0.y), nu0y = splat2(-u0.y);
                u64 u1x = splat2(u1.x), u1y = splat2(u1.y), nu1y = splat2(-u1.y);
                u64 u2x = splat2(u2.x), u2y = splat2(u2.y), nu2y = splat2(-u2.y);
                u64 u3x = splat2(u3.x), u3y = splat2(u3.y), nu3y = splat2(-u3.y);
                #pragma unroll
                for (int pr = 0; pr < 2; pr++) {
                    int a = (bp == 1) ? (pr * 2) : pr;
                    int c = (bp == 1) ? (pr * 2 + 1) : (pr + 2);
                    u64 ax = xv[a], ay = yv[a], bx = xv[c], by = yv[c];
                    xv[a] = fma2(u0x, ax, fma2(nu0y, ay, fma2(u1x, bx, mul2(nu1y, by))));
                    yv[a] = fma2(u0x, ay, fma2(u0y, ax, fma2(u1x, by, mul2(u1y, bx))));
                    xv[c] = fma2(u2x, ax, fma2(nu2y, ay, fma2(u3x, bx, mul2(nu3y, by))));
                    yv[c] = fma2(u2x, ay, fma2(u2y, ax, fma2(u3x, by, mul2(u3y, bx))));
                }
            } else {
                u64 Ax = pack2(u0.x, u3.x), Ay = pack2(u0.y, u3.y), nAy = pack2(-u0.y, -u3.y);
                u64 Bx = pack2(u1.x, u2.x), By = pack2(u1.y, u2.y), nBy = pack2(-u1.y, -u2.y);
                #pragma unroll
                for (int v = 0; v < 4; v++) {
                    u64 xs_ = swap2(xv[v]);
                    u64 ys_ = swap2(yv[v]);
                    u64 nx = fma2(Ax, xv[v], fma2(nAy, yv[v], fma2(Bx, xs_, mul2(nBy, ys_))));
                    u64 ny = fma2(Ax, yv[v], fma2(Ay, xv[v], fma2(Bx, ys_, mul2(By, xs_))));
                    xv[v] = nx; yv[v] = ny;
                }
            }
        }
        __syncwarp();
        #pragma unroll
        for (int v = 0; v < 4; v++) {
            float2 rx = unpack2(xv[v]), ry = unpack2(yv[v]);
            sre[w][(2 * v) * 32 + l]      = rx.x;
            sre[w][(2 * v + 1) * 32 + l]  = rx.y;
            sim_[w][(2 * v) * 32 + l]     = ry.x;
            sim_[w][(2 * v + 1) * 32 + l] = ry.y;
        }
        __syncwarp();
        #pragma unroll
        for (int v = 0; v < 4; v++) {
            xv[v] = pack2(sre[w][rslot[2 * v]], sre[w][rslot[2 * v + 1]]);
            yv[v] = pack2(sim_[w][rslot[2 * v]], sim_[w][rslot[2 * v + 1]]);
        }
    }

    #pragma unroll
    for (int v = 0; v < 4; v++) {
        float2 rx = unpack2(xv[v]), ry = unpack2(yv[v]);
        int j0 = 8 * l + 2 * v;
        float vals[4] = {rx.x, ry.x, rx.y, ry.y};
        #pragma unroll
        for (int r = 0; r < 4; r++)
            g_Wh[(size_t)(2 * j0 + r) * 256 + k] = __float2half_rn(vals[r]);
    }
}

// ---------------- K2: fp16 mma.sync GEMM (W x) + expectation epilogue --------
#define GEMM_SMEM 65536   // 2 stages x (A 16KB + B 16KB)

__global__ __launch_bounds__(256) void k_gemm(int B) {
    extern __shared__ __align__(16) char smg[];
    uint32_t sb = smem_to_u32(smg);
    int tid = threadIdx.x;
    int w = tid >> 5, l = tid & 31;
    int tile = blockIdx.x >> 2, nb = blockIdx.x & 3;
    int S0 = tile * 128;

    int r8 = l & 7, grp = l >> 3;
    int rowA = r8 + ((grp & 1) << 3);
    int colA = (grp & 2) << 3;
    int rowB = l & 7;
    int colB = ((l >> 3) & 1) << 4;

    float acc[8][2][4];
    #pragma unroll
    for (int mt = 0; mt < 8; mt++)
        #pragma unroll
        for (int nt = 0; nt < 2; nt++)
            #pragma unroll
            for (int c = 0; c < 4; c++) acc[mt][nt][c] = 0.f;

    #define LOAD_STAGE(kc, st) do { \
        int base_ = (st) * 32768; \
        for (int i = tid; i < 1024; i += 256) { \
            int row_ = i >> 3, seg_ = i & 7; \
            uint32_t dst_ = SWZ((uint32_t)(row_ * 128 + seg_ * 16)); \
            const __half* sA_ = g_xh + (size_t)(S0 + row_) * 256 + (kc) * 64 + seg_ * 8; \
            const __half* sB_ = g_Wh + (size_t)(nb * 128 + row_) * 256 + (kc) * 64 + seg_ * 8; \
            CP_ASYNC16(sb + base_ + dst_, sA_); \
            CP_ASYNC16(sb + base_ + 16384 + dst_, sB_); \
        } \
        CP_COMMIT(); \
    } while (0)

    LOAD_STAGE(0, 0);
    for (int kc = 0; kc < 4; kc++) {
        if (kc < 3) { LOAD_STAGE(kc + 1, (kc + 1) & 1); CP_WAIT(1); }
        else        { CP_WAIT(0); }
        __syncthreads();
        uint32_t base = sb + (kc & 1) * 32768;
        #pragma unroll
        for (int ks = 0; ks < 4; ks++) {
            uint32_t bh[2][2];
            #pragma unroll
            for (int nt = 0; nt < 2; nt++) {
                uint32_t boff = SWZ((uint32_t)((w * 16 + nt * 8 + rowB) * 128 + ks * 32 + colB));
                LDMX2(bh[nt], base + 16384 + boff);
            }
            #pragma unroll
            for (int mt = 0; mt < 8; mt++) {
                uint32_t aoff = SWZ((uint32_t)((mt * 16 + rowA) * 128 + ks * 32 + colA));
                uint32_t ah[4];
                LDMX4(ah, base + aoff);
                #pragma unroll
                for (int nt = 0; nt < 2; nt++)
                    MMA_F16(acc[mt][nt], ah, bh[nt]);
            }
        }
        __syncthreads();
    }

    float* e_s = (float*)smg;
    #pragma unroll
    for (int mt = 0; mt < 8; mt++) {
        float sa0 = 0.f, sa1 = 0.f, sa2 = 0.f, sa3 = 0.f;
        float sb0 = 0.f, sb1 = 0.f, sb2 = 0.f, sb3 = 0.f;
        #pragma unroll
        for (int nt = 0; nt < 2; nt++) {
            float c0 = acc[mt][nt][0], c1 = acc[mt][nt][1];
            float c2 = acc[mt][nt][2], c3 = acc[mt][nt][3];
            float Pa = c0 * c0 + c1 * c1;
            float Pb = c2 * c2 + c3 * c3;
            int j = nb * 64 + w * 8 + nt * 4 + (l & 3);
            float f0 = (j & 128) ? -1.f : 1.f;
            float f1 = (j & 64)  ? -1.f : 1.f;
            float f2 = (j & 32)  ? -1.f : 1.f;
            float f3 = (j & 16)  ? -1.f : 1.f;
            sa0 += f0 * Pa; sa1 += f1 * Pa; sa2 += f2 * Pa; sa3 += f3 * Pa;
            sb0 += f0 * Pb; sb1 += f1 * Pb; sb2 += f2 * Pb; sb3 += f3 * Pb;
        }
        #define REDL(v) { v += __shfl_xor_sync(0xffffffffu, v, 1); v += __shfl_xor_sync(0xffffffffu, v, 2); }
        REDL(sa0) REDL(sa1) REDL(sa2) REDL(sa3)
        REDL(sb0) REDL(sb1) REDL(sb2) REDL(sb3)
        if ((l & 3) == 0) {
            int m1 = mt * 16 + (l >> 2);
            float* p1 = e_s + (w * 128 + m1) * 4;
            p1[0] = sa0; p1[1] = sa1; p1[2] = sa2; p1[3] = sa3;
            float* p2 = e_s + (w * 128 + m1 + 8) * 4;
            p2[0] = sb0; p2[1] = sb1; p2[2] = sb2; p2[3] = sb3;
        }
    }
    __syncthreads();
    if (tid < 128) {
        float4 r = make_float4(0.f, 0.f, 0.f, 0.f);
        #pragma unroll
        for (int w8 = 0; w8 < 8; w8++) {
            const float* p = e_s + (w8 * 128 + tid) * 4;
            r.x += p[0]; r.y += p[1]; r.z += p[2]; r.w += p[3];
        }
        g_eqp4[nb * MAXB + S0 + tid] = r;
    }
}

// ---------------- K3: fused feat + BN1 + fc2 + BN2 + tail (2 global barriers)
#define FEAT_SMEM (64*260*4 + 64*68*4 + 2048)
// post-GEMM aliases inside the dynamic buffer:
//   h1s  @ 0      (64x68 f32 = 17408)
//   hs   @ 20480  (64x8   = 2048)
//   ys   @ 24576  (64x33  = 8448)
//   ys2  @ 36864  (64x17  = 4352)
//   w2s  @ 41216  (512 f32 = 2048)
//   b2s  @ 43264  (16)
//   bns  @ 43328  (64)
//   red1 @ 43584  (4x64 = 1024)
//   tot1 @ 44608  (64)
//   wsum @ 44864  (8x8 = 256)
//   red2 @ 45120  (8x32 = 1024)
//   tot2 @ 46144  (32)
//   bn2  @ 46272  (32)
//   w3s  @ 46400  (128)
//   b3s  @ 46912  (8)
//   w4s  @ 46944  (8)
//   consts @ 83968 (persist from GEMM phase)

__global__ __launch_bounds__(256) void k_feat(
    const float* __restrict__ x,
    const float* __restrict__ aW, const float* __restrict__ ab,
    const float* __restrict__ fW1, const float* __restrict__ fb1,
    const float* __restrict__ fW2, const float* __restrict__ fb2,
    const float* __restrict__ cW1, const float* __restrict__ cb1,
    const float* __restrict__ g1,  const float* __restrict__ be1,
    const float* __restrict__ cW2, const float* __restrict__ cb2,
    const float* __restrict__ g2,  const float* __restrict__ be2,
    const float* __restrict__ cW3, const float* __restrict__ cb3,
    const float* __restrict__ cW4, const float* __restrict__ cb4,
    float* __restrict__ out, int B)
{
    extern __shared__ __align__(16) char sm[];
    float (*xs)[260] = (float(*)[260])sm;
    float (*ws)[68]  = (float(*)[68])(sm + 66560);
    float *cst       = (float*)(sm + 83968);
    float *fw2s = cst;
    float *cw1s = cst + 256;
    float *fb1s = cst + 384;
    float *cb1s = cst + 448;
    float *fb2s = cst + 480;
    float *abs_ = cst + 484;
    float *aWs  = cst + 488;
    float (*h1s)[68] = (float(*)[68])sm;
    float (*hs)[8]   = (float(*)[8])(sm + 20480);
    float (*ys)[33]  = (float(*)[33])(sm + 24576);
    float (*ys2)[17] = (float(*)[17])(sm + 36864);
    float *w2s  = (float*)(sm + 41216);
    float *b2s  = (float*)(sm + 43264);
    float *bns  = (float*)(sm + 43328);
    float (*red1)[64] = (float(*)[64])(sm + 43584);
    float *tot1 = (float*)(sm + 44608);
    float (*wsum)[8]  = (float(*)[8])(sm + 44864);
    float (*red2)[32] = (float(*)[32])(sm + 45120);
    float *tot2 = (float*)(sm + 46144);
    float *bn2  = (float*)(sm + 46272);
    float *w3s  = (float*)(sm + 46400);
    float *b3s  = (float*)(sm + 46912);
    float *w4s  = (float*)(sm + 46944);

    int tid = threadIdx.x;
    int S0 = blockIdx.x * 64;
    int w = tid >> 5, l = tid & 31;

    fw2s[tid] = fW2[tid];
    if (tid < 128) cw1s[tid] = cW1[tid];
    if (tid < 64)  fb1s[tid] = fb1[tid];
    if (tid < 32)  cb1s[tid] = cb1[tid];
    if (tid < 16)  aWs[tid]  = aW[tid];
    if (tid < 4) { fb2s[tid] = fb2[tid]; abs_[tid] = ab[tid]; }

    for (int i = tid; i < 64 * 64; i += 256) {
        int s = i >> 6, q = i & 63;
        ((float4*)&xs[s][0])[q] = ((const float4*)(x + (size_t)(S0 + s) * 256))[q];
    }

    u64 acc[2][8];
    #pragma unroll
    for (int sg = 0; sg < 2; sg++)
        #pragma unroll
        for (int j = 0; j < 8; j++) acc[sg][j] = 0ull;

    for (int kc = 0; kc < 4; kc++) {
        __syncthreads();
        for (int i = tid; i < 64 * 16; i += 256) {
            int o = i >> 4, q = i & 15;
            ((float4*)&ws[o][0])[q] = ((const float4*)(fW1 + o * 256 + kc * 64))[q];
        }
        __syncthreads();
        const float4* xr0 = (const float4*)&xs[l][kc * 64];
        const float4* xr1 = (const float4*)&xs[l + 32][kc * 64];
        #pragma unroll
        for (int q = 0; q < 16; q++) {
            float4 a4 = xr0[q], b4 = xr1[q];
            u64 x0lo = pack2(a4.x, a4.y), x0hi = pack2(a4.z, a4.w);
            u64 x1lo = pack2(b4.x, b4.y), x1hi = pack2(b4.z, b4.w);
            #pragma unroll
            for (int j = 0; j < 8; j++) {
                float4 w4 = ((const float4*)&ws[w * 8 + j][0])[q];
                u64 wlo = pack2(w4.x, w4.y), whi = pack2(w4.z, w4.w);
                acc[0][j] = fma2(wlo, x0lo, acc[0][j]);
                acc[0][j] = fma2(whi, x0hi, acc[0][j]);
                acc[1][j] = fma2(wlo, x1lo, acc[1][j]);
                acc[1][j] = fma2(whi, x1hi, acc[1][j]);
            }
        }
    }
    __syncthreads();

    #pragma unroll
    for (int sg = 0; sg < 2; sg++) {
        int s = l + 32 * sg;
        #pragma unroll
        for (int j = 0; j < 8; j++) {
            float2 r = unpack2(acc[sg][j]);
            h1s[s][w * 8 + j] = fmaxf(r.x + r.y + fb1s[w * 8 + j], 0.f);
        }
    }
    // load tail weights while h1s settles
    for (int i = tid; i < 512; i += 256) w2s[i] = cW2[i];
    if (tid < 128) w3s[tid] = cW3[tid];
    if (tid < 16)  b2s[tid] = cb2[tid];
    if (tid < 8) { b3s[tid] = cb3[tid]; w4s[tid] = cW4[tid]; }
    __syncthreads();

    {
        int s = tid & 63, j = tid >> 6;
        float a = fb2s[j];
        const float4* hp = (const float4*)&h1s[s][0];
        const float4* wp = (const float4*)&fw2s[j * 64];
        #pragma unroll
        for (int q = 0; q < 16; q++) {
            float4 h = hp[q], wv = wp[q];
            a += h.x * wv.x + h.y * wv.y + h.z * wv.z + h.w * wv.w;
        }
        float cf = tanhf(a);
        float4 q0 = g_eqp4[0 * MAXB + S0 + s];
        float4 q1 = g_eqp4[1 * MAXB + S0 + s];
        float4 q2 = g_eqp4[2 * MAXB + S0 + s];
        float4 q3 = g_eqp4[3 * MAXB + S0 + s];
        float inv = 1.f / g_nrm2[S0 + s];
        float qx = (q0.x + q1.x + q2.x + q3.x) * inv;
        float qy = (q0.y + q1.y + q2.y + q3.y) * inv;
        float qz = (q0.z + q1.z + q2.z + q3.z) * inv;
        float qw = (q0.w + q1.w + q2.w + q3.w) * inv;
        float qf = abs_[j] + aWs[j * 4 + 0] * qx + aWs[j * 4 + 1] * qy
                           + aWs[j * 4 + 2] * qz + aWs[j * 4 + 3] * qw;
        hs[s][j] = cf + qf;
    }
    __syncthreads();

    // y1 = cW1 @ h + cb1 -> ys (smem only)
    for (int i = tid; i < 64 * 32; i += 256) {
        int s = i >> 5, o = i & 31;
        float vv = cb1s[o];
        #pragma unroll
        for (int k = 0; k < 4; k++) vv += hs[s][k] * cw1s[o * 4 + k];
        ys[s][o] = vv;
    }
    __syncthreads();

    // BN1 partials
    if (tid < 32) {
        float su = 0.f, sq = 0.f;
        #pragma unroll
        for (int s = 0; s < 64; s++) {
            float vv = ys[s][tid];
            su += vv; sq += vv * vv;
        }
        g_part1[blockIdx.x * 64 + tid]      = su;
        g_part1[blockIdx.x * 64 + 32 + tid] = sq;
    }

    GLOBAL_BARRIER(g_arr1, g_dep1);

    // BN1 finalize (redundant per block); __ldcg: cross-SM data within launch
    {
        int c = tid & 63, rp = tid >> 6;
        int NB = B / 64;
        float sv = 0.f;
        for (int bb = rp; bb < NB; bb += 4) sv += __ldcg(&g_part1[bb * 64 + c]);
        red1[rp][c] = sv;
    }
    __syncthreads();
    if (tid < 64) tot1[tid] = red1[0][tid] + red1[1][tid] + red1[2][tid] + red1[3][tid];
    __syncthreads();
    if (tid < 32) {
        float invB  = 1.f / (float)B;
        float mean  = tot1[tid] * invB;
        float var   = tot1[32 + tid] * invB - mean * mean;
        float scale = g1[tid] * rsqrtf(var + 1e-5f);
        bns[tid]      = scale;
        bns[32 + tid] = be1[tid] - mean * scale;
    }
    __syncthreads();

    // fc2: thread (s = tid&63, jq = tid>>6) computes y2[s][jq*4..+4)
    int s2 = tid & 63, jq = tid >> 6;
    float y2v[4];
    {
        float zloc[32];
        #pragma unroll
        for (int o = 0; o < 32; o++)
            zloc[o] = fmaxf(ys[s2][o] * bns[o] + bns[32 + o], 0.f);
        #pragma unroll
        for (int jj = 0; jj < 4; jj++) {
            int j = jq * 4 + jj;
            float a = b2s[j];
            #pragma unroll
            for (int o = 0; o < 32; o++) a += zloc[o] * w2s[j * 32 + o];
            y2v[jj] = a;
            ys2[s2][j] = a;
        }
    }
    // BN2 partials: warp w holds samples (w&1)*32+l, j's jq=w>>1
    {
        float su[4], sq[4];
        #pragma unroll
        for (int jj = 0; jj < 4; jj++) { su[jj] = y2v[jj]; sq[jj] = y2v[jj] * y2v[jj]; }
        #pragma unroll
        for (int o = 16; o; o >>= 1) {
            #pragma unroll
            for (int jj = 0; jj < 4; jj++) {
                su[jj] += __shfl_xor_sync(0xffffffffu, su[jj], o);
                sq[jj] += __shfl_xor_sync(0xffffffffu, sq[jj], o);
            }
        }
        if (l == 0) {
            #pragma unroll
            for (int jj = 0; jj < 4; jj++) { wsum[w][jj] = su[jj]; wsum[w][4 + jj] = sq[jj]; }
        }
    }
    __syncthreads();
    if (tid < 32) {
        int j = tid & 15, kind = tid >> 4;
        int jq2 = j >> 2, jj = j & 3;
        g_part2[blockIdx.x * 32 + tid] =
            wsum[jq2 * 2][kind * 4 + jj] + wsum[jq2 * 2 + 1][kind * 4 + jj];
    }

    GLOBAL_BARRIER(g_arr2, g_dep2);

    // BN2 finalize
    {
        int c = tid & 31, rp = tid >> 5;
        int NB2 = B / 64;
        float sv = 0.f;
        for (int bb = rp; bb < NB2; bb += 8) sv += __ldcg(&g_part2[bb * 32 + c]);
        red2[rp][c] = sv;
    }
    __syncthreads();
    if (tid < 32) {
        float tt = 0.f;
        #pragma unroll
        for (int rp = 0; rp < 8; rp++) tt += red2[rp][tid];
        tot2[tid] = tt;
    }
    __syncthreads();
    if (tid < 16) {
        float invB  = 1.f / (float)B;
        float mean  = tot2[tid] * invB;
        float var   = tot2[16 + tid] * invB - mean * mean;
        float scale = g2[tid] * rsqrtf(var + 1e-5f);
        bn2[tid]      = scale;
        bn2[16 + tid] = be2[tid] - mean * scale;
    }
    __syncthreads();

    // tail: threads 0..63, one sample each
    if (tid < 64) {
        float z2[16];
        #pragma unroll
        for (int j = 0; j < 16; j++)
            z2[j] = fmaxf(ys2[tid][j] * bn2[j] + bn2[16 + j], 0.f);
        float o = cb4[0];
        #pragma unroll
        for (int j = 0; j < 8; j++) {
            float a = b3s[j];
            #pragma unroll
            for (int k = 0; k < 16; k++) a += z2[k] * w3s[j * 16 + k];
            o += fmaxf(a, 0.f) * w4s[j];
        }
        out[S0 + tid] = 1.f / (1.f + expf(-o));
    }
}

// ---------------- launch ------------------------------------------------------
extern "C" void kernel_launch(void* const* d_in, const int* in_sizes, int n_in,
                              void* d_out, int out_size) {
    const float* x    = (const float*)d_in[0];
    const float* qw   = (const float*)d_in[1];
    const float* aW   = (const float*)d_in[2];
    const float* ab   = (const float*)d_in[3];
    const float* fW1  = (const float*)d_in[4];
    const float* fb1  = (const float*)d_in[5];
    const float* fW2  = (const float*)d_in[6];
    const float* fb2  = (const float*)d_in[7];
    const float* cW1  = (const float*)d_in[8];
    const float* cb1  = (const float*)d_in[9];
    const float* g1   = (const float*)d_in[10];
    const float* be1  = (const float*)d_in[11];
    const float* cW2  = (const float*)d_in[12];
    const float* cb2  = (const float*)d_in[13];
    const float* g2   = (const float*)d_in[14];
    const float* be2  = (const float*)d_in[15];
    const float* cW3  = (const float*)d_in[16];
    const float* cb3  = (const float*)d_in[17];
    const float* cW4  = (const float*)d_in[18];
    const float* cb4  = (const float*)d_in[19];

    int B = in_sizes[0] / 256;
    int convB = B / 8;

    cudaFuncSetAttribute(k_feat, cudaFuncAttributeMaxDynamicSharedMemorySize, FEAT_SMEM);
    cudaFuncSetAttribute(k_gemm, cudaFuncAttributeMaxDynamicSharedMemorySize, GEMM_SMEM);

    k_prep<<<convB + 32, 256>>>(x, qw, convB);
    k_gemm<<<(B / 128) * 4, 256, GEMM_SMEM>>>(B);
    k_feat<<<B / 64, 256, FEAT_SMEM>>>(x, aW, ab, fW1, fb1, fW2, fb2, cW1, cb1,
                                       g1, be1, cW2, cb2, g2, be2, cW3, cb3, cW4, cb4,
                                       (float*)d_out, B);
}